// round 1
// baseline (speedup 1.0000x reference)
#include <cuda_runtime.h>

#define NB 8
#define NN 256
#define ND 128
#define NH 256
#define NK 128

// ---------------- scratch (static device globals; no allocation) ----------
__device__ float  g_hi[NB*NN*NH];      // hi + b1 folded in   (2 MB)
__device__ float  g_hj[NB*NN*NH];      // hj                  (2 MB)
__device__ float2 g_mb[NB*NN*NN];      // (mul, bias) per pair (4 MB)

// ---------------- Kernel A: hi' = A@W1[:D] + b1 ; hj = A@W1[D:] ------------
__global__ void k_embed(const float* __restrict__ ae,
                        const float* __restrict__ W1,
                        const float* __restrict__ b1) {
    int row = blockIdx.x;                  // 0..2047  = (b*N + n)
    __shared__ float a[ND];
    int t = threadIdx.x;                   // 0..255 (output h index)
    if (t < ND) a[t] = ae[row*ND + t];
    __syncthreads();

    float acc1 = b1[t];
    float acc2 = 0.f;
    #pragma unroll 4
    for (int k = 0; k < ND; k++) {
        float av = a[k];
        acc1 = fmaf(av, W1[k*NH + t],        acc1);
        acc2 = fmaf(av, W1[(ND + k)*NH + t], acc2);
    }
    g_hi[row*NH + t] = acc1;
    g_hj[row*NH + t] = acc2;
}

// ---------------- Kernel B: pair MLP -> (mul, bias) ------------------------
// 64 threads, each owns a 2x2 pair tile -> block tile = 16(i) x 16(j).
// smem: 2 * 16 * 260 * 4B = 33.3 KB + 2 KB weights (under 48 KB static).
#define TI 16
#define TJ 16
#define PADH 260

#define KB_STEP(A0,A1,C0,C1,W0,W1v) {                                   \
    float r00 = fmaxf((A0) + (C0), 0.f);                                 \
    float r01 = fmaxf((A0) + (C1), 0.f);                                 \
    float r10 = fmaxf((A1) + (C0), 0.f);                                 \
    float r11 = fmaxf((A1) + (C1), 0.f);                                 \
    acc00a = fmaf(r00, (W0), acc00a); acc00b = fmaf(r00, (W1v), acc00b); \
    acc01a = fmaf(r01, (W0), acc01a); acc01b = fmaf(r01, (W1v), acc01b); \
    acc10a = fmaf(r10, (W0), acc10a); acc10b = fmaf(r10, (W1v), acc10b); \
    acc11a = fmaf(r11, (W0), acc11a); acc11b = fmaf(r11, (W1v), acc11b); }

__global__ void k_pairs(const float* __restrict__ W2,
                        const float* __restrict__ b2) {
    __shared__ float shi[TI][PADH];
    __shared__ float shj[TJ][PADH];
    __shared__ float sw0[NH];
    __shared__ float sw1[NH];

    int b  = blockIdx.z;
    int i0 = blockIdx.y * TI;
    int j0 = blockIdx.x * TJ;
    int tid = threadIdx.x;                 // 0..63

    const float* hi_base = g_hi + (size_t)(b*NN + i0)*NH;
    const float* hj_base = g_hj + (size_t)(b*NN + j0)*NH;

    // cooperative tile load (coalesced float4)
    for (int idx = tid; idx < TI*(NH/4); idx += 64) {
        int r = idx / (NH/4);
        int c = idx % (NH/4);
        float4 v = ((const float4*)hi_base)[r*(NH/4) + c];
        *(float4*)&shi[r][c*4] = v;
        float4 w = ((const float4*)hj_base)[r*(NH/4) + c];
        *(float4*)&shj[r][c*4] = w;
    }
    for (int h = tid; h < NH; h += 64) {
        sw0[h] = W2[2*h];
        sw1[h] = W2[2*h + 1];
    }
    __syncthreads();

    int tjj = tid & 7;                     // 0..7
    int tii = tid >> 3;                    // 0..7

    float acc00a=0.f, acc00b=0.f, acc01a=0.f, acc01b=0.f;
    float acc10a=0.f, acc10b=0.f, acc11a=0.f, acc11b=0.f;

    #pragma unroll 2
    for (int h4 = 0; h4 < NH/4; h4++) {
        float4 a0 = *(const float4*)&shi[tii*2 + 0][h4*4];
        float4 a1 = *(const float4*)&shi[tii*2 + 1][h4*4];
        float4 c0 = *(const float4*)&shj[tjj*2 + 0][h4*4];
        float4 c1 = *(const float4*)&shj[tjj*2 + 1][h4*4];
        float4 w0 = *(const float4*)&sw0[h4*4];
        float4 w1 = *(const float4*)&sw1[h4*4];
        KB_STEP(a0.x, a1.x, c0.x, c1.x, w0.x, w1.x);
        KB_STEP(a0.y, a1.y, c0.y, c1.y, w0.y, w1.y);
        KB_STEP(a0.z, a1.z, c0.z, c1.z, w0.z, w1.z);
        KB_STEP(a0.w, a1.w, c0.w, c1.w, w0.w, w1.w);
    }

    const float s = 0.0625f;               // 1/sqrt(2*128)
    float cb0 = b2[0] * s;
    float cb1 = b2[1] * s;
    int i = i0 + tii*2;
    int j = j0 + tjj*2;
    size_t base = (size_t)(b*NN + i)*NN + j;
    g_mb[base]          = make_float2(fmaf(acc00a, s, cb0), fmaf(acc00b, s, cb1));
    g_mb[base + 1]      = make_float2(fmaf(acc01a, s, cb0), fmaf(acc01b, s, cb1));
    g_mb[base + NN]     = make_float2(fmaf(acc10a, s, cb0), fmaf(acc10b, s, cb1));
    g_mb[base + NN + 1] = make_float2(fmaf(acc11a, s, cb0), fmaf(acc11b, s, cb1));
}

// ---------------- Kernel C: RBF expansion + output write -------------------
__device__ __forceinline__ float ex2a(float v) {
    float y;
    asm("ex2.approx.f32 %0, %1;" : "=f"(y) : "f"(v));
    return y;
}

__global__ void k_rbf(const float* __restrict__ x,
                      const float* __restrict__ means,
                      const float* __restrict__ temps,
                      float* __restrict__ out) {
    int lane = threadIdx.x & 31;
    int wid  = threadIdx.x >> 5;           // 0..7
    int k0 = lane * 4;

    const float L2E = 1.4426950408889634f;
    float m0 = means[k0+0], m1 = means[k0+1], m2 = means[k0+2], m3 = means[k0+3];
    float n0 = -fabsf(temps[k0+0]) * L2E;
    float n1 = -fabsf(temps[k0+1]) * L2E;
    float n2 = -fabsf(temps[k0+2]) * L2E;
    float n3 = -fabsf(temps[k0+3]) * L2E;

    int pbase = blockIdx.x * 64 + wid;      // warp handles 8 pairs, stride 8
    #pragma unroll
    for (int it = 0; it < 8; it++) {
        int p = pbase + it * 8;
        float2 mb = g_mb[p];
        float xv  = __ldg(&x[p]);
        float v = fmaf(mb.x, xv, mb.y);

        float d0 = v - m0;
        float d1 = v - m1;
        float d2 = v - m2;
        float d3 = v - m3;
        float e0 = ex2a(d0*d0*n0);
        float e1 = ex2a(d1*d1*n1);
        float e2 = ex2a(d2*d2*n2);
        float e3 = ex2a(d3*d3*n3);

        *(float4*)(out + (((size_t)p) << 7) + k0) = make_float4(e0, e1, e2, e3);
    }
}

// ---------------- launch ----------------------------------------------------
extern "C" void kernel_launch(void* const* d_in, const int* in_sizes, int n_in,
                              void* d_out, int out_size) {
    const float* x     = (const float*)d_in[0];   // (B,N,N)
    const float* ae    = (const float*)d_in[1];   // (B,N,D)
    const float* W1    = (const float*)d_in[2];   // (2D,H)
    const float* b1    = (const float*)d_in[3];   // (H)
    const float* W2    = (const float*)d_in[4];   // (H,2)
    const float* b2    = (const float*)d_in[5];   // (2)
    const float* means = (const float*)d_in[6];   // (K)
    const float* temps = (const float*)d_in[7];   // (K)
    float* out = (float*)d_out;                   // (B,N,N,K)

    k_embed<<<NB*NN, NH>>>(ae, W1, b1);

    dim3 gB(NN/TJ, NN/TI, NB);                    // (16, 16, 8)
    k_pairs<<<gB, 64>>>(W2, b2);

    k_rbf<<<NB*NN*NN/64, 256>>>(x, means, temps, out);
}

// round 2
// speedup vs baseline: 1.0591x; 1.0591x over previous
#include <cuda_runtime.h>

#define NB 8
#define NN 256
#define ND 128
#define NH 256
#define NK 128

// ---------------- scratch ----------------------------------------------------
__device__ float g_hi[NB*NN*NH];      // hi + b1 folded in   (2 MB)
__device__ float g_hj[NB*NN*NH];      // hj                  (2 MB)

// ---------------- Kernel A: hi' = A@W1[:D] + b1 ; hj = A@W1[D:] --------------
// 256 blocks x 8 rows. Each thread owns one h column for 8 rows:
// W1 loaded once per (k,t), reused for 8 rows from registers (16 FMA / 2 LDG).
#define ROWS 8
__global__ void k_embed(const float* __restrict__ ae,
                        const float* __restrict__ W1,
                        const float* __restrict__ b1) {
    __shared__ float a[ROWS][ND];          // 4 KB
    int row0 = blockIdx.x * ROWS;
    int t = threadIdx.x;                   // h index 0..255

    // cooperative A-tile load: 8*128 floats = 256 float4, one per thread
    {
        int r = t >> 5;                    // 0..7
        int c = t & 31;                    // 0..31
        *(float4*)&a[r][c*4] = *(const float4*)&ae[(size_t)(row0 + r)*ND + c*4];
    }
    __syncthreads();

    float b1t = b1[t];
    float acci[ROWS], accj[ROWS];
    #pragma unroll
    for (int r = 0; r < ROWS; r++) { acci[r] = b1t; accj[r] = 0.f; }

    for (int k4 = 0; k4 < ND/4; k4++) {
        float4 av[ROWS];
        #pragma unroll
        for (int r = 0; r < ROWS; r++) av[r] = *(const float4*)&a[r][k4*4];
        int k = k4 * 4;
        #pragma unroll
        for (int u = 0; u < 4; u++) {
            float w1a = W1[(size_t)(k+u)*NH + t];
            float w1b = W1[(size_t)(ND+k+u)*NH + t];
            #pragma unroll
            for (int r = 0; r < ROWS; r++) {
                float av_u = (u==0) ? av[r].x : (u==1) ? av[r].y : (u==2) ? av[r].z : av[r].w;
                acci[r] = fmaf(av_u, w1a, acci[r]);
                accj[r] = fmaf(av_u, w1b, accj[r]);
            }
        }
    }

    #pragma unroll
    for (int r = 0; r < ROWS; r++) {
        g_hi[(size_t)(row0 + r)*NH + t] = acci[r];
        g_hj[(size_t)(row0 + r)*NH + t] = accj[r];
    }
}

// ---------------- Kernel B: fused pair-MLP + RBF + output write --------------
#define TI 16
#define TJ 16
#define PADH 260

__device__ __forceinline__ float ex2a(float v) {
    float y;
    asm("ex2.approx.f32 %0, %1;" : "=f"(y) : "f"(v));
    return y;
}

#define KB_STEP(A0,A1,C0,C1,W0,W1v) {                                   \
    float r00 = fmaxf((A0) + (C0), 0.f);                                 \
    float r01 = fmaxf((A0) + (C1), 0.f);                                 \
    float r10 = fmaxf((A1) + (C0), 0.f);                                 \
    float r11 = fmaxf((A1) + (C1), 0.f);                                 \
    acc00a = fmaf(r00, (W0), acc00a); acc00b = fmaf(r00, (W1v), acc00b); \
    acc01a = fmaf(r01, (W0), acc01a); acc01b = fmaf(r01, (W1v), acc01b); \
    acc10a = fmaf(r10, (W0), acc10a); acc10b = fmaf(r10, (W1v), acc10b); \
    acc11a = fmaf(r11, (W0), acc11a); acc11b = fmaf(r11, (W1v), acc11b); }

__global__ void k_fused(const float* __restrict__ x,
                        const float* __restrict__ W2,
                        const float* __restrict__ b2,
                        const float* __restrict__ means,
                        const float* __restrict__ temps,
                        float* __restrict__ out) {
    __shared__ float shi[TI][PADH];        // 16.6 KB
    __shared__ float shj[TJ][PADH];        // 16.6 KB
    __shared__ float sw0[NH];              // 1 KB
    __shared__ float sw1[NH];              // 1 KB
    __shared__ float smul[TI*TJ];          // 1 KB
    __shared__ float sbias[TI*TJ];         // 1 KB
    __shared__ float sx[TI*TJ];            // 1 KB

    int b  = blockIdx.z;
    int i0 = blockIdx.y * TI;
    int j0 = blockIdx.x * TJ;
    int tid  = threadIdx.x;                // 0..63
    int lane = tid & 31;
    int wid  = tid >> 5;                   // 0..1

    // per-lane RBF constants: lane owns k0 = lane*4
    const float L2E = 1.4426950408889634f;
    int k0 = lane * 4;
    float m0 = __ldg(&means[k0+0]), m1 = __ldg(&means[k0+1]);
    float m2 = __ldg(&means[k0+2]), m3 = __ldg(&means[k0+3]);
    float n0 = -fabsf(__ldg(&temps[k0+0])) * L2E;
    float n1 = -fabsf(__ldg(&temps[k0+1])) * L2E;
    float n2 = -fabsf(__ldg(&temps[k0+2])) * L2E;
    float n3 = -fabsf(__ldg(&temps[k0+3])) * L2E;

    const float* hi_base = g_hi + (size_t)(b*NN + i0)*NH;
    const float* hj_base = g_hj + (size_t)(b*NN + j0)*NH;

    // cooperative tile loads (coalesced float4)
    for (int idx = tid; idx < TI*(NH/4); idx += 64) {
        int r = idx / (NH/4);
        int c = idx % (NH/4);
        *(float4*)&shi[r][c*4] = ((const float4*)hi_base)[r*(NH/4) + c];
        *(float4*)&shj[r][c*4] = ((const float4*)hj_base)[r*(NH/4) + c];
    }
    for (int h = tid; h < NH; h += 64) {
        sw0[h] = W2[2*h];
        sw1[h] = W2[2*h + 1];
    }
    // x tile: 16 rows x 16 cols, one float4 per thread
    {
        int r = tid >> 2;                  // 0..15
        int c = tid & 3;                   // 0..3
        *(float4*)&sx[r*TJ + c*4] =
            *(const float4*)&x[(size_t)(b*NN + i0 + r)*NN + j0 + c*4];
    }
    __syncthreads();

    // ---------- phase 1: pair MLP, 2x2 tile per thread ----------
    int tjj = tid & 7;
    int tii = tid >> 3;

    float acc00a=0.f, acc00b=0.f, acc01a=0.f, acc01b=0.f;
    float acc10a=0.f, acc10b=0.f, acc11a=0.f, acc11b=0.f;

    #pragma unroll 2
    for (int h4 = 0; h4 < NH/4; h4++) {
        float4 a0 = *(const float4*)&shi[tii*2 + 0][h4*4];
        float4 a1 = *(const float4*)&shi[tii*2 + 1][h4*4];
        float4 c0 = *(const float4*)&shj[tjj*2 + 0][h4*4];
        float4 c1 = *(const float4*)&shj[tjj*2 + 1][h4*4];
        float4 w0 = *(const float4*)&sw0[h4*4];
        float4 w1 = *(const float4*)&sw1[h4*4];
        KB_STEP(a0.x, a1.x, c0.x, c1.x, w0.x, w1.x);
        KB_STEP(a0.y, a1.y, c0.y, c1.y, w0.y, w1.y);
        KB_STEP(a0.z, a1.z, c0.z, c1.z, w0.z, w1.z);
        KB_STEP(a0.w, a1.w, c0.w, c1.w, w0.w, w1.w);
    }

    {
        const float s = 0.0625f;           // 1/sqrt(2*128)
        float cb0 = b2[0] * s;
        float cb1 = b2[1] * s;
        int pi = tii*2, pj = tjj*2;
        smul [(pi  )*TJ + pj  ] = fmaf(acc00a, s, cb0);
        sbias[(pi  )*TJ + pj  ] = fmaf(acc00b, s, cb1);
        smul [(pi  )*TJ + pj+1] = fmaf(acc01a, s, cb0);
        sbias[(pi  )*TJ + pj+1] = fmaf(acc01b, s, cb1);
        smul [(pi+1)*TJ + pj  ] = fmaf(acc10a, s, cb0);
        sbias[(pi+1)*TJ + pj  ] = fmaf(acc10b, s, cb1);
        smul [(pi+1)*TJ + pj+1] = fmaf(acc11a, s, cb0);
        sbias[(pi+1)*TJ + pj+1] = fmaf(acc11b, s, cb1);
    }
    __syncthreads();

    // ---------- phase 2: RBF + store. Warp sweeps pairs, lane owns k. -------
    // Each warp STG.128 writes one contiguous 512B output row.
    size_t obase = ((size_t)(b*NN + i0)*NN + j0) * NK + k0;
    int p0 = wid * 128;
    #pragma unroll 4
    for (int pp = 0; pp < 128; pp++) {
        int p = p0 + pp;
        float v = fmaf(smul[p], sx[p], sbias[p]);
        float d0 = v - m0;
        float d1 = v - m1;
        float d2 = v - m2;
        float d3 = v - m3;
        float e0 = ex2a(d0*d0*n0);
        float e1 = ex2a(d1*d1*n1);
        float e2 = ex2a(d2*d2*n2);
        float e3 = ex2a(d3*d3*n3);
        int i = p >> 4, j = p & 15;
        *(float4*)(out + obase + ((size_t)i*NN + j)*NK) = make_float4(e0, e1, e2, e3);
    }
}

// ---------------- launch ------------------------------------------------------
extern "C" void kernel_launch(void* const* d_in, const int* in_sizes, int n_in,
                              void* d_out, int out_size) {
    const float* x     = (const float*)d_in[0];   // (B,N,N)
    const float* ae    = (const float*)d_in[1];   // (B,N,D)
    const float* W1    = (const float*)d_in[2];   // (2D,H)
    const float* b1    = (const float*)d_in[3];   // (H)
    const float* W2    = (const float*)d_in[4];   // (H,2)
    const float* b2    = (const float*)d_in[5];   // (2)
    const float* means = (const float*)d_in[6];   // (K)
    const float* temps = (const float*)d_in[7];   // (K)
    float* out = (float*)d_out;                   // (B,N,N,K)

    k_embed<<<NB*NN/ROWS, NH>>>(ae, W1, b1);

    dim3 gB(NN/TJ, NN/TI, NB);                    // (16, 16, 8)
    k_fused<<<gB, 64>>>(x, W2, b2, means, temps, out);
}

// round 3
// speedup vs baseline: 1.4091x; 1.3304x over previous
#include <cuda_runtime.h>

#define NB 8
#define NN 256
#define ND 128
#define NH 256
#define NK 128

// ---------------- scratch ----------------------------------------------------
__device__ float g_hi[NB*NN*NH];      // hi + b1 folded in   (2 MB)
__device__ float g_hj[NB*NN*NH];      // hj                  (2 MB)

// ---------------- Kernel A: hi' = A@W1[:D] + b1 ; hj = A@W1[D:] --------------
// grid (256, 2): block = 8 rows x 128 h-cols. 128 threads; thread owns a
// float4 h-quad for 2 rows (vectorized W1 LDG.128, 16 FMA per 2 loads).
#define EROWS 8
__global__ void k_embed(const float* __restrict__ ae,
                        const float* __restrict__ W1,
                        const float* __restrict__ b1) {
    __shared__ float sa[EROWS][ND];        // 4 KB
    int row0 = blockIdx.x * EROWS;
    int hbase = blockIdx.y * 128;
    int tid = threadIdx.x;                 // 0..127

    // cooperative A-tile load: 8*128 floats = 256 float4
    #pragma unroll
    for (int idx = tid; idx < EROWS*ND/4; idx += 128) {
        int r = idx >> 5;
        int c = idx & 31;
        *(float4*)&sa[r][c*4] = *(const float4*)&ae[(size_t)(row0 + r)*ND + c*4];
    }
    __syncthreads();

    int hq = tid & 31;                     // h-quad within the 128-col half
    int rg = tid >> 5;                     // 0..3 -> rows rg*2, rg*2+1
    int h  = hbase + hq*4;
    int r0 = rg*2;

    float4 bb = *(const float4*)&b1[h];
    float4 ai0 = bb, ai1 = bb;
    float4 aj0 = make_float4(0.f,0.f,0.f,0.f), aj1 = aj0;

    #pragma unroll 2
    for (int k = 0; k < ND; k++) {
        float4 wa = *(const float4*)&W1[(size_t)k*NH + h];
        float4 wb = *(const float4*)&W1[(size_t)(ND + k)*NH + h];
        float a0 = sa[r0][k];
        float a1 = sa[r0+1][k];
        ai0.x = fmaf(a0, wa.x, ai0.x); ai0.y = fmaf(a0, wa.y, ai0.y);
        ai0.z = fmaf(a0, wa.z, ai0.z); ai0.w = fmaf(a0, wa.w, ai0.w);
        ai1.x = fmaf(a1, wa.x, ai1.x); ai1.y = fmaf(a1, wa.y, ai1.y);
        ai1.z = fmaf(a1, wa.z, ai1.z); ai1.w = fmaf(a1, wa.w, ai1.w);
        aj0.x = fmaf(a0, wb.x, aj0.x); aj0.y = fmaf(a0, wb.y, aj0.y);
        aj0.z = fmaf(a0, wb.z, aj0.z); aj0.w = fmaf(a0, wb.w, aj0.w);
        aj1.x = fmaf(a1, wb.x, aj1.x); aj1.y = fmaf(a1, wb.y, aj1.y);
        aj1.z = fmaf(a1, wb.z, aj1.z); aj1.w = fmaf(a1, wb.w, aj1.w);
    }

    *(float4*)&g_hi[(size_t)(row0 + r0  )*NH + h] = ai0;
    *(float4*)&g_hi[(size_t)(row0 + r0+1)*NH + h] = ai1;
    *(float4*)&g_hj[(size_t)(row0 + r0  )*NH + h] = aj0;
    *(float4*)&g_hj[(size_t)(row0 + r0+1)*NH + h] = aj1;
}

// ---------------- Kernel B: fused pair-MLP + RBF + output write --------------
// 32x32 pair tile, 256 threads, each owns pairs (tii+{0,16}) x (tjj+{0,16}).
// h-dim processed in 2 chunks of 128 to halve smem. smul/sbias alias shi.
#define TI 32
#define TJ 32
#define HCH 128
#define PAD 132

__device__ __forceinline__ float ex2a(float v) {
    float y;
    asm("ex2.approx.f32 %0, %1;" : "=f"(y) : "f"(v));
    return y;
}

#define KB_STEP(A0,A1,C0,C1,W0,W1v) {                                   \
    float r00 = fmaxf((A0) + (C0), 0.f);                                 \
    float r01 = fmaxf((A0) + (C1), 0.f);                                 \
    float r10 = fmaxf((A1) + (C0), 0.f);                                 \
    float r11 = fmaxf((A1) + (C1), 0.f);                                 \
    acc00a = fmaf(r00, (W0), acc00a); acc00b = fmaf(r00, (W1v), acc00b); \
    acc01a = fmaf(r01, (W0), acc01a); acc01b = fmaf(r01, (W1v), acc01b); \
    acc10a = fmaf(r10, (W0), acc10a); acc10b = fmaf(r10, (W1v), acc10b); \
    acc11a = fmaf(r11, (W0), acc11a); acc11b = fmaf(r11, (W1v), acc11b); }

__global__ __launch_bounds__(256) void k_fused(
        const float* __restrict__ x,
        const float* __restrict__ W2,
        const float* __restrict__ b2,
        const float* __restrict__ means,
        const float* __restrict__ temps,
        float* __restrict__ out) {
    __shared__ float shi[TI*PAD];          // 16.9 KB, reused for smul/sbias
    __shared__ float shj[TJ*PAD];          // 16.9 KB
    __shared__ float sw0[NH];              // 1 KB
    __shared__ float sw1[NH];              // 1 KB
    __shared__ float sx[TI*TJ];            // 4 KB

    int b  = blockIdx.z;
    int i0 = blockIdx.y * TI;
    int j0 = blockIdx.x * TJ;
    int tid  = threadIdx.x;                // 0..255
    int lane = tid & 31;
    int wid  = tid >> 5;                   // 0..7

    // per-lane RBF constants: lane owns k0 = lane*4
    const float L2E = 1.4426950408889634f;
    int k0 = lane * 4;
    float m0 = __ldg(&means[k0+0]), m1 = __ldg(&means[k0+1]);
    float m2 = __ldg(&means[k0+2]), m3 = __ldg(&means[k0+3]);
    float n0 = -fabsf(__ldg(&temps[k0+0])) * L2E;
    float n1 = -fabsf(__ldg(&temps[k0+1])) * L2E;
    float n2 = -fabsf(__ldg(&temps[k0+2])) * L2E;
    float n3 = -fabsf(__ldg(&temps[k0+3])) * L2E;

    // one-time loads: W2 columns and x tile
    for (int h = tid; h < NH; h += 256) {
        sw0[h] = W2[2*h];
        sw1[h] = W2[2*h + 1];
    }
    {
        int r = tid >> 3;                  // 0..31
        int c = tid & 7;                   // 0..7
        *(float4*)&sx[r*TJ + c*4] =
            *(const float4*)&x[(size_t)(b*NN + i0 + r)*NN + j0 + c*4];
    }

    const float* hi_base = g_hi + (size_t)(b*NN + i0)*NH;
    const float* hj_base = g_hj + (size_t)(b*NN + j0)*NH;

    int tjj = tid & 15;                    // j rows tjj, tjj+16
    int tii = tid >> 4;                    // i rows tii, tii+16

    float acc00a=0.f, acc00b=0.f, acc01a=0.f, acc01b=0.f;
    float acc10a=0.f, acc10b=0.f, acc11a=0.f, acc11b=0.f;

    #pragma unroll
    for (int p = 0; p < 2; p++) {
        __syncthreads();
        // load h-chunk: 32 rows x 128 floats each for hi and hj
        #pragma unroll
        for (int idx = tid; idx < TI*(HCH/4); idx += 256) {
            int r = idx >> 5;              // 32 float4 per row
            int c = idx & 31;
            *(float4*)&shi[r*PAD + c*4] = *(const float4*)&hi_base[(size_t)r*NH + p*HCH + c*4];
            *(float4*)&shj[r*PAD + c*4] = *(const float4*)&hj_base[(size_t)r*NH + p*HCH + c*4];
        }
        __syncthreads();

        const float* wp0 = sw0 + p*HCH;
        const float* wp1 = sw1 + p*HCH;
        #pragma unroll 2
        for (int h4 = 0; h4 < HCH/4; h4++) {
            float4 a0 = *(const float4*)&shi[(tii   )*PAD + h4*4];
            float4 a1 = *(const float4*)&shi[(tii+16)*PAD + h4*4];
            float4 c0 = *(const float4*)&shj[(tjj   )*PAD + h4*4];
            float4 c1 = *(const float4*)&shj[(tjj+16)*PAD + h4*4];
            float4 w0 = *(const float4*)&wp0[h4*4];
            float4 w1 = *(const float4*)&wp1[h4*4];
            KB_STEP(a0.x, a1.x, c0.x, c1.x, w0.x, w1.x);
            KB_STEP(a0.y, a1.y, c0.y, c1.y, w0.y, w1.y);
            KB_STEP(a0.z, a1.z, c0.z, c1.z, w0.z, w1.z);
            KB_STEP(a0.w, a1.w, c0.w, c1.w, w0.w, w1.w);
        }
    }

    __syncthreads();                       // shi reads done; safe to alias
    float* smul  = shi;                    // [0..1023]
    float* sbias = shi + TI*TJ;            // [1024..2047]
    {
        const float s = 0.0625f;           // 1/sqrt(2*128)
        float cb0 = b2[0] * s;
        float cb1 = b2[1] * s;
        int pi0 = tii, pi1 = tii + 16;
        int pj0 = tjj, pj1 = tjj + 16;
        smul [pi0*TJ + pj0] = fmaf(acc00a, s, cb0);
        sbias[pi0*TJ + pj0] = fmaf(acc00b, s, cb1);
        smul [pi0*TJ + pj1] = fmaf(acc01a, s, cb0);
        sbias[pi0*TJ + pj1] = fmaf(acc01b, s, cb1);
        smul [pi1*TJ + pj0] = fmaf(acc10a, s, cb0);
        sbias[pi1*TJ + pj0] = fmaf(acc10b, s, cb1);
        smul [pi1*TJ + pj1] = fmaf(acc11a, s, cb0);
        sbias[pi1*TJ + pj1] = fmaf(acc11b, s, cb1);
    }
    __syncthreads();

    // ---------- phase 2: RBF + store. Warp sweeps 128 pairs, lane owns k. ----
    size_t obase = ((size_t)(b*NN + i0)*NN + j0) * NK + k0;
    int p0 = wid * 128;
    #pragma unroll 4
    for (int pp = 0; pp < 128; pp++) {
        int p = p0 + pp;
        float v = fmaf(smul[p], sx[p], sbias[p]);
        float d0 = v - m0;
        float d1 = v - m1;
        float d2 = v - m2;
        float d3 = v - m3;
        float e0 = ex2a(d0*d0*n0);
        float e1 = ex2a(d1*d1*n1);
        float e2 = ex2a(d2*d2*n2);
        float e3 = ex2a(d3*d3*n3);
        int i = p >> 5, j = p & 31;
        __stcs((float4*)(out + obase + ((size_t)i*NN + j)*NK),
               make_float4(e0, e1, e2, e3));
    }
}

// ---------------- launch ------------------------------------------------------
extern "C" void kernel_launch(void* const* d_in, const int* in_sizes, int n_in,
                              void* d_out, int out_size) {
    const float* x     = (const float*)d_in[0];   // (B,N,N)
    const float* ae    = (const float*)d_in[1];   // (B,N,D)
    const float* W1    = (const float*)d_in[2];   // (2D,H)
    const float* b1    = (const float*)d_in[3];   // (H)
    const float* W2    = (const float*)d_in[4];   // (H,2)
    const float* b2    = (const float*)d_in[5];   // (2)
    const float* means = (const float*)d_in[6];   // (K)
    const float* temps = (const float*)d_in[7];   // (K)
    float* out = (float*)d_out;                   // (B,N,N,K)

    dim3 gA(NB*NN/EROWS, 2);                      // (256, 2)
    k_embed<<<gA, 128>>>(ae, W1, b1);

    dim3 gB(NN/TJ, NN/TI, NB);                    // (8, 8, 8)
    k_fused<<<gB, 256>>>(x, W2, b2, means, temps, out);
}

// round 4
// speedup vs baseline: 1.7372x; 1.2329x over previous
#include <cuda_runtime.h>

#define NB 8
#define NN 256
#define ND 128
#define NH 256
#define NK 128

// ---------------- scratch ----------------------------------------------------
__device__ float g_hi[NB*NN*NH];      // hi + b1 folded in   (2 MB)
__device__ float g_hj[NB*NN*NH];      // hj                  (2 MB)

// ---------------- Kernel A: [2048x128] @ [128x512] with smem-staged W1 -------
// Flat 512 output cols = [hi(256) | hj(256)]. Block = 32 rows x 64 cols,
// 128 threads: thread owns 4 rows x 1 col-quad (16 FMA per 20B of LDS).
// W1 k-chunks staged in smem -> W1 L2 traffic drops 4x vs round-3.
__global__ __launch_bounds__(128) void k_embed(const float* __restrict__ ae,
                                               const float* __restrict__ W1,
                                               const float* __restrict__ b1) {
    __shared__ float sa[32][129];          // 16.5 KB (pad 1: conflict-free a reads)
    __shared__ float wseg[64][64];         // 16 KB  (k-chunk x 64 cols)

    int row0  = blockIdx.x * 32;
    int hcol0 = blockIdx.y * 64;           // flat col 0..511
    bool isb  = hcol0 >= 256;
    int gcol  = hcol0 & 255;
    int tid   = threadIdx.x;
    int hq    = tid & 15;                  // col quad 0..15
    int rg    = tid >> 4;                  // 0..7 -> rows rg*4..rg*4+3

    // stage A tile 32x128 (float4 global loads, scalar smem stores for pad)
    #pragma unroll
    for (int s = 0; s < 8; s++) {
        int idx = s*128 + tid;             // 1024 float4
        int r = idx >> 5, q = idx & 31;
        float4 v = *(const float4*)&ae[(size_t)(row0 + r)*ND + q*4];
        sa[r][q*4+0] = v.x; sa[r][q*4+1] = v.y;
        sa[r][q*4+2] = v.z; sa[r][q*4+3] = v.w;
    }

    float4 bb = isb ? make_float4(0.f,0.f,0.f,0.f)
                    : *(const float4*)&b1[gcol + hq*4];
    float4 acc0 = bb, acc1 = bb, acc2 = bb, acc3 = bb;

    const float* wbase = W1 + (size_t)(isb ? 128 : 0)*NH + gcol;

    #pragma unroll
    for (int kc = 0; kc < 128; kc += 64) {
        __syncthreads();
        #pragma unroll
        for (int s = 0; s < 8; s++) {
            int idx = s*128 + tid;         // 1024 float4 = 64 k x 16 quads
            int kk = idx >> 4, q = idx & 15;
            *(float4*)&wseg[kk][q*4] =
                *(const float4*)&wbase[(size_t)(kc + kk)*NH + q*4];
        }
        __syncthreads();

        #pragma unroll 4
        for (int kk = 0; kk < 64; kk++) {
            float4 w = *(const float4*)&wseg[kk][hq*4];
            float a0 = sa[rg*4+0][kc+kk];
            float a1 = sa[rg*4+1][kc+kk];
            float a2 = sa[rg*4+2][kc+kk];
            float a3 = sa[rg*4+3][kc+kk];
            acc0.x = fmaf(a0,w.x,acc0.x); acc0.y = fmaf(a0,w.y,acc0.y);
            acc0.z = fmaf(a0,w.z,acc0.z); acc0.w = fmaf(a0,w.w,acc0.w);
            acc1.x = fmaf(a1,w.x,acc1.x); acc1.y = fmaf(a1,w.y,acc1.y);
            acc1.z = fmaf(a1,w.z,acc1.z); acc1.w = fmaf(a1,w.w,acc1.w);
            acc2.x = fmaf(a2,w.x,acc2.x); acc2.y = fmaf(a2,w.y,acc2.y);
            acc2.z = fmaf(a2,w.z,acc2.z); acc2.w = fmaf(a2,w.w,acc2.w);
            acc3.x = fmaf(a3,w.x,acc3.x); acc3.y = fmaf(a3,w.y,acc3.y);
            acc3.z = fmaf(a3,w.z,acc3.z); acc3.w = fmaf(a3,w.w,acc3.w);
        }
    }

    float* dst = isb ? g_hj : g_hi;
    int c = (isb ? hcol0 - 256 : hcol0) + hq*4;
    int r0 = row0 + rg*4;
    *(float4*)&dst[(size_t)(r0+0)*NH + c] = acc0;
    *(float4*)&dst[(size_t)(r0+1)*NH + c] = acc1;
    *(float4*)&dst[(size_t)(r0+2)*NH + c] = acc2;
    *(float4*)&dst[(size_t)(r0+3)*NH + c] = acc3;
}

// ---------------- Kernel B: fused pair-MLP + RBF + output write --------------
// 32(i) x 16(j) pair tile, 128 threads, 2x2 per thread (i: tii,tii+16; j: tjj,tjj+8).
// grid = 1024 blocks (~6.9/SM) so blocks in different phases overlap pipes.
#define TI 32
#define TJ 16
#define HCH 128
#define PAD 132

__device__ __forceinline__ float ex2a(float v) {
    float y;
    asm("ex2.approx.f32 %0, %1;" : "=f"(y) : "f"(v));
    return y;
}

#define KB_STEP(A0,A1,C0,C1,W0,W1v) {                                   \
    float r00 = fmaxf((A0) + (C0), 0.f);                                 \
    float r01 = fmaxf((A0) + (C1), 0.f);                                 \
    float r10 = fmaxf((A1) + (C0), 0.f);                                 \
    float r11 = fmaxf((A1) + (C1), 0.f);                                 \
    acc00a = fmaf(r00, (W0), acc00a); acc00b = fmaf(r00, (W1v), acc00b); \
    acc01a = fmaf(r01, (W0), acc01a); acc01b = fmaf(r01, (W1v), acc01b); \
    acc10a = fmaf(r10, (W0), acc10a); acc10b = fmaf(r10, (W1v), acc10b); \
    acc11a = fmaf(r11, (W0), acc11a); acc11b = fmaf(r11, (W1v), acc11b); }

__global__ __launch_bounds__(128) void k_fused(
        const float* __restrict__ x,
        const float* __restrict__ W2,
        const float* __restrict__ b2,
        const float* __restrict__ means,
        const float* __restrict__ temps,
        float* __restrict__ out) {
    __shared__ float shi[TI*PAD];          // 16.9 KB, reused for smul/sbias
    __shared__ float shj[TJ*PAD];          // 8.4 KB
    __shared__ float sw0[NH];              // 1 KB
    __shared__ float sw1[NH];              // 1 KB
    __shared__ float sx[TI*TJ];            // 2 KB

    int b  = blockIdx.z;
    int i0 = blockIdx.y * TI;
    int j0 = blockIdx.x * TJ;
    int tid  = threadIdx.x;                // 0..127
    int lane = tid & 31;
    int wid  = tid >> 5;                   // 0..3

    // per-lane RBF constants (polynomial form): arg = n*v^2 + p*v + q
    // n = -|t|*log2e ; p = -2*n*m ; q = n*m^2
    const float L2E = 1.4426950408889634f;
    int k0 = lane * 4;
    float4 mm4 = *(const float4*)&means[k0];
    float4 tt4 = *(const float4*)&temps[k0];
    float nA0 = -fabsf(tt4.x)*L2E, nA1 = -fabsf(tt4.y)*L2E;
    float nA2 = -fabsf(tt4.z)*L2E, nA3 = -fabsf(tt4.w)*L2E;
    float pB0 = -2.f*nA0*mm4.x, pB1 = -2.f*nA1*mm4.y;
    float pB2 = -2.f*nA2*mm4.z, pB3 = -2.f*nA3*mm4.w;
    float qC0 = nA0*mm4.x*mm4.x, qC1 = nA1*mm4.y*mm4.y;
    float qC2 = nA2*mm4.z*mm4.z, qC3 = nA3*mm4.w*mm4.w;

    // one-time loads: W2 columns and x tile
    #pragma unroll
    for (int h = tid; h < NH; h += 128) {
        sw0[h] = W2[2*h];
        sw1[h] = W2[2*h + 1];
    }
    {
        int r = tid >> 2;                  // 0..31
        int c = tid & 3;                   // 0..3
        *(float4*)&sx[r*TJ + c*4] =
            *(const float4*)&x[(size_t)(b*NN + i0 + r)*NN + j0 + c*4];
    }

    const float* hi_base = g_hi + (size_t)(b*NN + i0)*NH;
    const float* hj_base = g_hj + (size_t)(b*NN + j0)*NH;

    int tjj = tid & 7;                     // j rows tjj, tjj+8
    int tii = tid >> 3;                    // i rows tii, tii+16

    float acc00a=0.f, acc00b=0.f, acc01a=0.f, acc01b=0.f;
    float acc10a=0.f, acc10b=0.f, acc11a=0.f, acc11b=0.f;

    #pragma unroll
    for (int p = 0; p < 2; p++) {
        __syncthreads();
        // stage h-chunk: shi 32x128, shj 16x128 (1536 float4 total)
        #pragma unroll
        for (int s = 0; s < 12; s++) {
            int idx = s*128 + tid;
            if (idx < 1024) {
                int r = idx >> 5, c = idx & 31;
                *(float4*)&shi[r*PAD + c*4] =
                    *(const float4*)&hi_base[(size_t)r*NH + p*HCH + c*4];
            } else {
                int id2 = idx - 1024;
                int r = id2 >> 5, c = id2 & 31;
                *(float4*)&shj[r*PAD + c*4] =
                    *(const float4*)&hj_base[(size_t)r*NH + p*HCH + c*4];
            }
        }
        __syncthreads();

        const float* wp0 = sw0 + p*HCH;
        const float* wp1 = sw1 + p*HCH;
        #pragma unroll 2
        for (int h4 = 0; h4 < HCH/4; h4++) {
            float4 a0 = *(const float4*)&shi[(tii   )*PAD + h4*4];
            float4 a1 = *(const float4*)&shi[(tii+16)*PAD + h4*4];
            float4 c0 = *(const float4*)&shj[(tjj   )*PAD + h4*4];
            float4 c1 = *(const float4*)&shj[(tjj+ 8)*PAD + h4*4];
            float4 w0 = *(const float4*)&wp0[h4*4];
            float4 w1 = *(const float4*)&wp1[h4*4];
            KB_STEP(a0.x, a1.x, c0.x, c1.x, w0.x, w1.x);
            KB_STEP(a0.y, a1.y, c0.y, c1.y, w0.y, w1.y);
            KB_STEP(a0.z, a1.z, c0.z, c1.z, w0.z, w1.z);
            KB_STEP(a0.w, a1.w, c0.w, c1.w, w0.w, w1.w);
        }
    }

    __syncthreads();                       // shi reads done; safe to alias
    float* smul  = shi;                    // 512 floats
    float* sbias = shi + TI*TJ;            // 512 floats (16B-aligned)
    {
        const float s = 0.0625f;           // 1/sqrt(2*128)
        float cb0 = b2[0] * s;
        float cb1 = b2[1] * s;
        smul [(tii   )*TJ + tjj  ] = fmaf(acc00a, s, cb0);
        sbias[(tii   )*TJ + tjj  ] = fmaf(acc00b, s, cb1);
        smul [(tii   )*TJ + tjj+8] = fmaf(acc01a, s, cb0);
        sbias[(tii   )*TJ + tjj+8] = fmaf(acc01b, s, cb1);
        smul [(tii+16)*TJ + tjj  ] = fmaf(acc10a, s, cb0);
        sbias[(tii+16)*TJ + tjj  ] = fmaf(acc10b, s, cb1);
        smul [(tii+16)*TJ + tjj+8] = fmaf(acc11a, s, cb0);
        sbias[(tii+16)*TJ + tjj+8] = fmaf(acc11b, s, cb1);
    }
    __syncthreads();

    // ---------- phase 2: RBF + store. Warp sweeps 128 pairs, lane owns 4 k. --
    size_t obase = ((size_t)(b*NN + i0)*NN + j0) * NK + k0;

    #define RBF_ELEM(M,X,BV,OP) {                                        \
        float v = fmaf((M), (X), (BV));                                   \
        float e0 = ex2a(fmaf(fmaf(nA0, v, pB0), v, qC0));                 \
        float e1 = ex2a(fmaf(fmaf(nA1, v, pB1), v, qC1));                 \
        float e2 = ex2a(fmaf(fmaf(nA2, v, pB2), v, qC2));                 \
        float e3 = ex2a(fmaf(fmaf(nA3, v, pB3), v, qC3));                 \
        __stcs((float4*)(OP), make_float4(e0, e1, e2, e3)); }

    #pragma unroll
    for (int ii = 0; ii < 8; ii++) {
        int i_loc = wid*8 + ii;            // 0..31
        const float4* m4p = (const float4*)smul  + i_loc*4;
        const float4* b4p = (const float4*)sbias + i_loc*4;
        const float4* x4p = (const float4*)sx    + i_loc*4;
        float* orow = out + obase + (size_t)i_loc*NN*NK;
        #pragma unroll
        for (int g = 0; g < 4; g++) {
            float4 m4 = m4p[g];
            float4 b4 = b4p[g];
            float4 xv = x4p[g];
            RBF_ELEM(m4.x, xv.x, b4.x, orow + (g*4+0)*NK);
            RBF_ELEM(m4.y, xv.y, b4.y, orow + (g*4+1)*NK);
            RBF_ELEM(m4.z, xv.z, b4.z, orow + (g*4+2)*NK);
            RBF_ELEM(m4.w, xv.w, b4.w, orow + (g*4+3)*NK);
        }
    }
}

// ---------------- launch ------------------------------------------------------
extern "C" void kernel_launch(void* const* d_in, const int* in_sizes, int n_in,
                              void* d_out, int out_size) {
    const float* x     = (const float*)d_in[0];   // (B,N,N)
    const float* ae    = (const float*)d_in[1];   // (B,N,D)
    const float* W1    = (const float*)d_in[2];   // (2D,H)
    const float* b1    = (const float*)d_in[3];   // (H)
    const float* W2    = (const float*)d_in[4];   // (H,2)
    const float* b2    = (const float*)d_in[5];   // (2)
    const float* means = (const float*)d_in[6];   // (K)
    const float* temps = (const float*)d_in[7];   // (K)
    float* out = (float*)d_out;                   // (B,N,N,K)

    dim3 gA(NB*NN/32, 8);                         // (64, 8) = 512 blocks
    k_embed<<<gA, 128>>>(ae, W1, b1);

    dim3 gB(NN/TJ, NN/TI, NB);                    // (16, 8, 8) = 1024 blocks
    k_fused<<<gB, 128>>>(x, W2, b2, means, temps, out);
}

// round 5
// speedup vs baseline: 1.7804x; 1.0248x over previous
#include <cuda_runtime.h>

#define NB 8
#define NN 256
#define ND 128
#define NH 256
#define NK 128

typedef unsigned long long u64t;

// ---------------- scratch ----------------------------------------------------
__device__ float g_hi[NB*NN*NH];      // hi + b1 folded in   (2 MB)
__device__ float g_hj[NB*NN*NH];      // hj                  (2 MB)

// ---------------- packed f32x2 helpers ---------------------------------------
__device__ __forceinline__ u64t add2(u64t a, u64t b) {
    u64t r; asm("add.rn.f32x2 %0, %1, %2;" : "=l"(r) : "l"(a), "l"(b)); return r;
}
__device__ __forceinline__ u64t fma2(u64t a, u64t b, u64t c) {
    u64t r; asm("fma.rn.f32x2 %0, %1, %2, %3;" : "=l"(r) : "l"(a), "l"(b), "l"(c)); return r;
}
__device__ __forceinline__ u64t relu2(u64t a) {
    float lo, hi;
    asm("mov.b64 {%0,%1}, %2;" : "=f"(lo), "=f"(hi) : "l"(a));
    lo = fmaxf(lo, 0.f); hi = fmaxf(hi, 0.f);
    u64t r; asm("mov.b64 %0, {%1,%2};" : "=l"(r) : "f"(lo), "f"(hi)); return r;
}
__device__ __forceinline__ float hsum2(u64t a) {
    float lo, hi;
    asm("mov.b64 {%0,%1}, %2;" : "=f"(lo), "=f"(hi) : "l"(a));
    return lo + hi;
}

// ---------------- Kernel A: [2048x128] @ [128x512] with smem-staged W1 -------
__global__ __launch_bounds__(128) void k_embed(const float* __restrict__ ae,
                                               const float* __restrict__ W1,
                                               const float* __restrict__ b1) {
    __shared__ float sa[32][129];
    __shared__ float wseg[64][64];

    int row0  = blockIdx.x * 32;
    int hcol0 = blockIdx.y * 64;
    bool isb  = hcol0 >= 256;
    int gcol  = hcol0 & 255;
    int tid   = threadIdx.x;
    int hq    = tid & 15;
    int rg    = tid >> 4;

    #pragma unroll
    for (int s = 0; s < 8; s++) {
        int idx = s*128 + tid;
        int r = idx >> 5, q = idx & 31;
        float4 v = *(const float4*)&ae[(size_t)(row0 + r)*ND + q*4];
        sa[r][q*4+0] = v.x; sa[r][q*4+1] = v.y;
        sa[r][q*4+2] = v.z; sa[r][q*4+3] = v.w;
    }

    float4 bb = isb ? make_float4(0.f,0.f,0.f,0.f)
                    : *(const float4*)&b1[gcol + hq*4];
    float4 acc0 = bb, acc1 = bb, acc2 = bb, acc3 = bb;

    const float* wbase = W1 + (size_t)(isb ? 128 : 0)*NH + gcol;

    #pragma unroll
    for (int kc = 0; kc < 128; kc += 64) {
        __syncthreads();
        #pragma unroll
        for (int s = 0; s < 8; s++) {
            int idx = s*128 + tid;
            int kk = idx >> 4, q = idx & 15;
            *(float4*)&wseg[kk][q*4] =
                *(const float4*)&wbase[(size_t)(kc + kk)*NH + q*4];
        }
        __syncthreads();

        #pragma unroll 4
        for (int kk = 0; kk < 64; kk++) {
            float4 w = *(const float4*)&wseg[kk][hq*4];
            float a0 = sa[rg*4+0][kc+kk];
            float a1 = sa[rg*4+1][kc+kk];
            float a2 = sa[rg*4+2][kc+kk];
            float a3 = sa[rg*4+3][kc+kk];
            acc0.x = fmaf(a0,w.x,acc0.x); acc0.y = fmaf(a0,w.y,acc0.y);
            acc0.z = fmaf(a0,w.z,acc0.z); acc0.w = fmaf(a0,w.w,acc0.w);
            acc1.x = fmaf(a1,w.x,acc1.x); acc1.y = fmaf(a1,w.y,acc1.y);
            acc1.z = fmaf(a1,w.z,acc1.z); acc1.w = fmaf(a1,w.w,acc1.w);
            acc2.x = fmaf(a2,w.x,acc2.x); acc2.y = fmaf(a2,w.y,acc2.y);
            acc2.z = fmaf(a2,w.z,acc2.z); acc2.w = fmaf(a2,w.w,acc2.w);
            acc3.x = fmaf(a3,w.x,acc3.x); acc3.y = fmaf(a3,w.y,acc3.y);
            acc3.z = fmaf(a3,w.z,acc3.z); acc3.w = fmaf(a3,w.w,acc3.w);
        }
    }

    float* dst = isb ? g_hj : g_hi;
    int c = (isb ? hcol0 - 256 : hcol0) + hq*4;
    int r0 = row0 + rg*4;
    *(float4*)&dst[(size_t)(r0+0)*NH + c] = acc0;
    *(float4*)&dst[(size_t)(r0+1)*NH + c] = acc1;
    *(float4*)&dst[(size_t)(r0+2)*NH + c] = acc2;
    *(float4*)&dst[(size_t)(r0+3)*NH + c] = acc3;
}

// ---------------- Kernel B: fused pair-MLP + RBF + output write --------------
#define TI 32
#define TJ 16
#define HCH 128
#define PAD 132

__device__ __forceinline__ float ex2a(float v) {
    float y;
    asm("ex2.approx.f32 %0, %1;" : "=f"(y) : "f"(v));
    return y;
}

// packed phase-1 step over one h-pair
#define PSTEP(A0,A1,C0,C1,W0,W1v) {                                     \
    u64t r00 = relu2(add2((A0), (C0)));                                  \
    u64t r01 = relu2(add2((A0), (C1)));                                  \
    u64t r10 = relu2(add2((A1), (C0)));                                  \
    u64t r11 = relu2(add2((A1), (C1)));                                  \
    acc00a = fma2(r00, (W0), acc00a); acc00b = fma2(r00, (W1v), acc00b); \
    acc01a = fma2(r01, (W0), acc01a); acc01b = fma2(r01, (W1v), acc01b); \
    acc10a = fma2(r10, (W0), acc10a); acc10b = fma2(r10, (W1v), acc10b); \
    acc11a = fma2(r11, (W0), acc11a); acc11b = fma2(r11, (W1v), acc11b); }

__global__ __launch_bounds__(128, 7) void k_fused(
        const float* __restrict__ x,
        const float* __restrict__ W2,
        const float* __restrict__ b2,
        const float* __restrict__ means,
        const float* __restrict__ temps,
        float* __restrict__ out) {
    __shared__ float shi[TI*PAD];          // 16.9 KB, reused for smul/sbias
    __shared__ float shj[TJ*PAD];          // 8.4 KB
    __shared__ float sw0[NH];              // 1 KB
    __shared__ float sw1[NH];              // 1 KB
    __shared__ float sx[TI*TJ];            // 2 KB

    int b  = blockIdx.z;
    int i0 = blockIdx.y * TI;
    int j0 = blockIdx.x * TJ;
    int tid  = threadIdx.x;                // 0..127
    int lane = tid & 31;
    int wid  = tid >> 5;                   // 0..3

    // one-time loads: W2 columns and x tile (smem only; few registers live)
    #pragma unroll
    for (int h = tid; h < NH; h += 128) {
        sw0[h] = W2[2*h];
        sw1[h] = W2[2*h + 1];
    }
    {
        int r = tid >> 2;
        int c = tid & 3;
        *(float4*)&sx[r*TJ + c*4] =
            *(const float4*)&x[(size_t)(b*NN + i0 + r)*NN + j0 + c*4];
    }

    const float* hi_base = g_hi + (size_t)(b*NN + i0)*NH;
    const float* hj_base = g_hj + (size_t)(b*NN + j0)*NH;

    int tjj = tid & 7;                     // j rows tjj, tjj+8
    int tii = tid >> 3;                    // i rows tii, tii+16

    u64t acc00a=0ull, acc00b=0ull, acc01a=0ull, acc01b=0ull;
    u64t acc10a=0ull, acc10b=0ull, acc11a=0ull, acc11b=0ull;

    #pragma unroll
    for (int p = 0; p < 2; p++) {
        __syncthreads();
        #pragma unroll
        for (int s = 0; s < 12; s++) {
            int idx = s*128 + tid;
            if (idx < 1024) {
                int r = idx >> 5, c = idx & 31;
                *(float4*)&shi[r*PAD + c*4] =
                    *(const float4*)&hi_base[(size_t)r*NH + p*HCH + c*4];
            } else {
                int id2 = idx - 1024;
                int r = id2 >> 5, c = id2 & 31;
                *(float4*)&shj[r*PAD + c*4] =
                    *(const float4*)&hj_base[(size_t)r*NH + p*HCH + c*4];
            }
        }
        __syncthreads();

        const float* wp0 = sw0 + p*HCH;
        const float* wp1 = sw1 + p*HCH;
        #pragma unroll 2
        for (int h4 = 0; h4 < HCH/4; h4++) {
            ulonglong2 A0 = *(const ulonglong2*)&shi[(tii   )*PAD + h4*4];
            ulonglong2 A1 = *(const ulonglong2*)&shi[(tii+16)*PAD + h4*4];
            ulonglong2 C0 = *(const ulonglong2*)&shj[(tjj   )*PAD + h4*4];
            ulonglong2 C1 = *(const ulonglong2*)&shj[(tjj+ 8)*PAD + h4*4];
            ulonglong2 W0 = *(const ulonglong2*)&wp0[h4*4];
            ulonglong2 W1v= *(const ulonglong2*)&wp1[h4*4];
            PSTEP(A0.x, A1.x, C0.x, C1.x, W0.x, W1v.x);
            PSTEP(A0.y, A1.y, C0.y, C1.y, W0.y, W1v.y);
        }
    }

    __syncthreads();                       // shi reads done; safe to alias
    float* smul  = shi;                    // 512 floats
    float* sbias = shi + TI*TJ;            // 512 floats
    {
        const float s = 0.0625f;           // 1/sqrt(2*128)
        float cb0 = b2[0] * s;
        float cb1 = b2[1] * s;
        smul [(tii   )*TJ + tjj  ] = fmaf(hsum2(acc00a), s, cb0);
        sbias[(tii   )*TJ + tjj  ] = fmaf(hsum2(acc00b), s, cb1);
        smul [(tii   )*TJ + tjj+8] = fmaf(hsum2(acc01a), s, cb0);
        sbias[(tii   )*TJ + tjj+8] = fmaf(hsum2(acc01b), s, cb1);
        smul [(tii+16)*TJ + tjj  ] = fmaf(hsum2(acc10a), s, cb0);
        sbias[(tii+16)*TJ + tjj  ] = fmaf(hsum2(acc10b), s, cb1);
        smul [(tii+16)*TJ + tjj+8] = fmaf(hsum2(acc11a), s, cb0);
        sbias[(tii+16)*TJ + tjj+8] = fmaf(hsum2(acc11b), s, cb1);
    }
    __syncthreads();

    // per-lane RBF constants, loaded only now (phase-local registers):
    // arg = n*v^2 + p*v + q ; n = -|t|*log2e ; p = -2*n*m ; q = n*m^2
    const float L2E = 1.4426950408889634f;
    int k0 = lane * 4;
    float4 mm4 = *(const float4*)&means[k0];
    float4 tt4 = *(const float4*)&temps[k0];
    float nA0 = -fabsf(tt4.x)*L2E, nA1 = -fabsf(tt4.y)*L2E;
    float nA2 = -fabsf(tt4.z)*L2E, nA3 = -fabsf(tt4.w)*L2E;
    float pB0 = -2.f*nA0*mm4.x, pB1 = -2.f*nA1*mm4.y;
    float pB2 = -2.f*nA2*mm4.z, pB3 = -2.f*nA3*mm4.w;
    float qC0 = nA0*mm4.x*mm4.x, qC1 = nA1*mm4.y*mm4.y;
    float qC2 = nA2*mm4.z*mm4.z, qC3 = nA3*mm4.w*mm4.w;

    size_t obase = ((size_t)(b*NN + i0)*NN + j0) * NK + k0;

    #define RBF_ELEM(M,X,BV,OP) {                                        \
        float v = fmaf((M), (X), (BV));                                   \
        float e0 = ex2a(fmaf(fmaf(nA0, v, pB0), v, qC0));                 \
        float e1 = ex2a(fmaf(fmaf(nA1, v, pB1), v, qC1));                 \
        float e2 = ex2a(fmaf(fmaf(nA2, v, pB2), v, qC2));                 \
        float e3 = ex2a(fmaf(fmaf(nA3, v, pB3), v, qC3));                 \
        __stcs((float4*)(OP), make_float4(e0, e1, e2, e3)); }

    #pragma unroll
    for (int ii = 0; ii < 8; ii++) {
        int i_loc = wid*8 + ii;            // 0..31
        const float4* m4p = (const float4*)smul  + i_loc*4;
        const float4* b4p = (const float4*)sbias + i_loc*4;
        const float4* x4p = (const float4*)sx    + i_loc*4;
        float* orow = out + obase + (size_t)i_loc*NN*NK;
        #pragma unroll
        for (int g = 0; g < 4; g++) {
            float4 m4 = m4p[g];
            float4 b4 = b4p[g];
            float4 xv = x4p[g];
            RBF_ELEM(m4.x, xv.x, b4.x, orow + (g*4+0)*NK);
            RBF_ELEM(m4.y, xv.y, b4.y, orow + (g*4+1)*NK);
            RBF_ELEM(m4.z, xv.z, b4.z, orow + (g*4+2)*NK);
            RBF_ELEM(m4.w, xv.w, b4.w, orow + (g*4+3)*NK);
        }
    }
}

// ---------------- launch ------------------------------------------------------
extern "C" void kernel_launch(void* const* d_in, const int* in_sizes, int n_in,
                              void* d_out, int out_size) {
    const float* x     = (const float*)d_in[0];   // (B,N,N)
    const float* ae    = (const float*)d_in[1];   // (B,N,D)
    const float* W1    = (const float*)d_in[2];   // (2D,H)
    const float* b1    = (const float*)d_in[3];   // (H)
    const float* W2    = (const float*)d_in[4];   // (H,2)
    const float* b2    = (const float*)d_in[5];   // (2)
    const float* means = (const float*)d_in[6];   // (K)
    const float* temps = (const float*)d_in[7];   // (K)
    float* out = (float*)d_out;                   // (B,N,N,K)

    dim3 gA(NB*NN/32, 8);                         // 512 blocks
    k_embed<<<gA, 128>>>(ae, W1, b1);

    dim3 gB(NN/TJ, NN/TI, NB);                    // 1024 blocks
    k_fused<<<gB, 128>>>(x, W2, b2, means, temps, out);
}